// round 11
// baseline (speedup 1.0000x reference)
#include <cuda_runtime.h>
#include <cuda_bf16.h>
#include <cuda_fp16.h>
#include <cstdint>
#include <math.h>

#define BB 4
#define SS 1024
#define EE 512
#define HH 512
#define VV 32000
#define MM (BB*SS)      // 4096
#define NH 8
#define DH 64

// ---------------- scratch (static device memory; no allocations) ----------------
__device__ float g_I[MM*HH];
__device__ float g_s[MM*HH];
__device__ float g_qkv[MM*3*HH];
__device__ __nv_bfloat16 g_Ahi[MM*HH],  g_Alo[MM*HH];
__device__ __nv_bfloat16 g_A2hi[MM*HH], g_A2lo[MM*HH];
__device__ __half        g_H2hi[MM*HH], g_H2lo[MM*HH];   // h2 fp16 (vocab A)
__device__ __nv_bfloat16 g_W0hi[HH*EE],  g_W0lo[HH*EE];
__device__ __nv_bfloat16 g_W1hi[HH*HH],  g_W1lo[HH*HH];
__device__ __nv_bfloat16 g_Wqhi[3*HH*HH], g_Wqlo[3*HH*HH];
__device__ __nv_bfloat16 g_Wohi[HH*HH],  g_Wolo[HH*HH];
__device__ __half        g_Bh[(size_t)VV*HH];            // vocab weights fp16
__device__ __nv_bfloat16 g_Qhi[32*1024*64], g_Qlo[32*1024*64];
__device__ __nv_bfloat16 g_Khi[32*1024*64], g_Klo[32*1024*64];
__device__ __half        g_Vth[32*128*1024];             // [bh][d pad128][k] fp16
__device__ __half        g_Sh[(size_t)32*1024*1024];     // scores/P fp16 (in-place)

__device__ __forceinline__ uint32_t smem_u32(const void* p) {
    uint32_t a;
    asm("{ .reg .u64 t; cvta.to.shared.u64 t, %1; cvt.u32.u64 %0, t; }" : "=r"(a) : "l"(p));
    return a;
}
__device__ __forceinline__ void cp_async16(uint32_t dst, const void* src) {
    asm volatile("cp.async.cg.shared.global [%0], [%1], 16;" :: "r"(dst), "l"(src));
}
__device__ __forceinline__ void ldsm_x4(uint32_t& r0, uint32_t& r1, uint32_t& r2, uint32_t& r3,
                                        uint32_t addr) {
    asm volatile("ldmatrix.sync.aligned.m8n8.x4.shared.b16 {%0,%1,%2,%3}, [%4];"
                 : "=r"(r0), "=r"(r1), "=r"(r2), "=r"(r3) : "r"(addr));
}
__device__ __forceinline__ void mma_bf16(float* c, const uint32_t* a, const uint32_t* b) {
    asm volatile("mma.sync.aligned.m16n8k16.row.col.f32.bf16.bf16.f32 "
                 "{%0,%1,%2,%3}, {%4,%5,%6,%7}, {%8,%9}, {%0,%1,%2,%3};"
                 : "+f"(c[0]), "+f"(c[1]), "+f"(c[2]), "+f"(c[3])
                 : "r"(a[0]), "r"(a[1]), "r"(a[2]), "r"(a[3]), "r"(b[0]), "r"(b[1]));
}
__device__ __forceinline__ void mma_f16(float* c, const uint32_t* a, const uint32_t* b) {
    asm volatile("mma.sync.aligned.m16n8k16.row.col.f32.f16.f16.f32 "
                 "{%0,%1,%2,%3}, {%4,%5,%6,%7}, {%8,%9}, {%0,%1,%2,%3};"
                 : "+f"(c[0]), "+f"(c[1]), "+f"(c[2]), "+f"(c[3])
                 : "r"(a[0]), "r"(a[1]), "r"(a[2]), "r"(a[3]), "r"(b[0]), "r"(b[1]));
}

// ---------------- embed + positional encoding -> bf16 hi/lo ----------------
__global__ void embed_pe_split(const int* __restrict__ x, const float* __restrict__ emb,
                               __nv_bfloat16* __restrict__ hi, __nv_bfloat16* __restrict__ lo) {
    int idx = blockIdx.x * blockDim.x + threadIdx.x;
    if (idx >= MM*EE) return;
    int m = idx >> 9;
    int e = idx & 511;
    int s = m & (SS - 1);
    int tok = x[m];
    int i2 = e & ~1;
    float freq = expf((float)i2 * (-9.210340371976184f / 512.0f));
    float ang = (float)s * freq;
    float pe = (e & 1) ? cosf(ang) : sinf(ang);
    float v = emb[(size_t)tok * EE + e] + pe;
    __nv_bfloat16 h = __float2bfloat16(v);
    hi[idx] = h;
    lo[idx] = __float2bfloat16(v - __bfloat162float(h));
}

__global__ void split_bf16_kernel(const float* __restrict__ in, __nv_bfloat16* __restrict__ hi,
                                  __nv_bfloat16* __restrict__ lo, int n) {
    int i = blockIdx.x * blockDim.x + threadIdx.x;
    if (i >= n) return;
    float x = in[i];
    __nv_bfloat16 h = __float2bfloat16(x);
    hi[i] = h;
    lo[i] = __float2bfloat16(x - __bfloat162float(h));
}

__global__ void convert_f16_kernel(const float* __restrict__ in, __half* __restrict__ out, int n) {
    int i = blockIdx.x * blockDim.x + threadIdx.x;
    if (i < n) out[i] = __float2half(in[i]);
}

// ============== bf16 3-term paired-operand NT GEMM ==============
#define SPAD 40
#define TILE_E (128*SPAD)
#define GP_SMEM (2*4*TILE_E*2)    // 81920 bytes

__global__ __launch_bounds__(256, 2) void gemm_pair_mma(
    const __nv_bfloat16* __restrict__ Ahi_, const __nv_bfloat16* __restrict__ Alo_,
    const __nv_bfloat16* __restrict__ Bhi_, const __nv_bfloat16* __restrict__ Blo_,
    const float* __restrict__ bias, float* __restrict__ C_,
    __half* __restrict__ Fhi_, __half* __restrict__ Flo_,
    int K, int lda, int ldb, int ldc, int nValid, float scale,
    int zmod, long long sA1, long long sA2, long long sB1, long long sB2,
    long long sC1, long long sC2)
{
    extern __shared__ __align__(16) __nv_bfloat16 sm[];
    const uint32_t smb = smem_u32(sm);

    const int tid = threadIdx.x;
    const int lane = tid & 31;
    const int wid = tid >> 5;
    const int warp_m = wid >> 2;
    const int warp_n = wid & 3;
    const int bm = blockIdx.y * 128;
    const int bn = blockIdx.x * 128;

    const int z = blockIdx.z;
    const int z1 = z % zmod, z2 = z / zmod;
    const long long offA = (long long)z1 * sA1 + (long long)z2 * sA2;
    const long long offB = (long long)z1 * sB1 + (long long)z2 * sB2;
    const long long offC = (long long)z1 * sC1 + (long long)z2 * sC2;

    const __nv_bfloat16* pA[2] = { Ahi_ + offA + (size_t)bm * lda,
                                   Alo_ + offA + (size_t)bm * lda };
    const __nv_bfloat16* pB[2] = { Bhi_ + offB + (size_t)bn * ldb,
                                   Blo_ + offB + (size_t)bn * ldb };

    float acc[4][4][4];
    #pragma unroll
    for (int i = 0; i < 4; i++)
        #pragma unroll
        for (int j = 0; j < 4; j++)
            #pragma unroll
            for (int r = 0; r < 4; r++) acc[i][j][r] = 0.f;

    const int lrow = tid >> 2;
    const int lcol = (tid & 3) * 8;
    const int nstages = K >> 5;

    auto prefetch = [&](int s) {
        const int gk = s * 32;
        const uint32_t base = smb + (uint32_t)((s & 1) * 4 * TILE_E) * 2;
        #pragma unroll
        for (int t = 0; t < 4; t++) {
            const __nv_bfloat16* src = (t < 2 ? pA[t] : pB[t-2]) + gk + lcol;
            const int ld = (t < 2) ? lda : ldb;
            #pragma unroll
            for (int c = 0; c < 2; c++) {
                int row = lrow + c * 64;
                cp_async16(base + (uint32_t)(t * TILE_E + row * SPAD + lcol) * 2,
                           src + (size_t)row * ld);
            }
        }
    };

    prefetch(0);
    asm volatile("cp.async.commit_group;");

    for (int s = 0; s < nstages; s++) {
        if (s < nstages - 1) {
            prefetch(s + 1);
            asm volatile("cp.async.commit_group;");
            asm volatile("cp.async.wait_group 1;");
        } else {
            asm volatile("cp.async.wait_group 0;");
        }
        __syncthreads();

        const uint32_t stg = smb + (uint32_t)((s & 1) * 4 * TILE_E) * 2;
        const uint32_t tAhi = stg;
        const uint32_t tAlo = stg + TILE_E * 2;
        const uint32_t tBhi = stg + 2 * TILE_E * 2;
        const uint32_t tBlo = stg + 3 * TILE_E * 2;
        const int q  = lane >> 3;
        const int rr = lane & 7;

        #pragma unroll
        for (int ko = 0; ko < 32; ko += 16) {
            const int arow = warp_m * 64 + (q & 1) * 8 + rr;
            const int acol = ko + (q >> 1) * 8;
            const int brow = warp_n * 32 + (q >> 1) * 8 + rr;
            const int bcol = ko + (q & 1) * 8;

            uint32_t aH[4][4];
            #pragma unroll
            for (int i = 0; i < 4; i++)
                ldsm_x4(aH[i][0], aH[i][1], aH[i][2], aH[i][3],
                        tAhi + (uint32_t)((arow + i * 16) * SPAD + acol) * 2);
            uint32_t bH[4][2], bL[4][2];
            #pragma unroll
            for (int j = 0; j < 2; j++) {
                ldsm_x4(bH[2*j][0], bH[2*j][1], bH[2*j+1][0], bH[2*j+1][1],
                        tBhi + (uint32_t)((brow + j * 16) * SPAD + bcol) * 2);
                ldsm_x4(bL[2*j][0], bL[2*j][1], bL[2*j+1][0], bL[2*j+1][1],
                        tBlo + (uint32_t)((brow + j * 16) * SPAD + bcol) * 2);
            }
            #pragma unroll
            for (int i = 0; i < 4; i++)
                #pragma unroll
                for (int j = 0; j < 4; j++)
                    mma_bf16(acc[i][j], aH[i], bH[j]);
            #pragma unroll
            for (int i = 0; i < 4; i++)
                #pragma unroll
                for (int j = 0; j < 4; j++)
                    mma_bf16(acc[i][j], aH[i], bL[j]);
            uint32_t aL[4][4];
            #pragma unroll
            for (int i = 0; i < 4; i++)
                ldsm_x4(aL[i][0], aL[i][1], aL[i][2], aL[i][3],
                        tAlo + (uint32_t)((arow + i * 16) * SPAD + acol) * 2);
            #pragma unroll
            for (int i = 0; i < 4; i++)
                #pragma unroll
                for (int j = 0; j < 4; j++)
                    mma_bf16(acc[i][j], aL[i], bH[j]);
        }
        __syncthreads();
    }

    // epilogue: fp32, fp16 hi/lo split, or single fp16
    const int gr = lane >> 2;
    const int gc = (lane & 3) * 2;
    float* C = C_ ? C_ + offC : nullptr;
    __half* Fhi = Fhi_ ? Fhi_ + offC : nullptr;
    __half* Flo = Flo_ ? Flo_ + offC : nullptr;

    #pragma unroll
    for (int j = 0; j < 4; j++) {
        int col = bn + warp_n * 32 + j * 8 + gc;
        if (col >= nValid) continue;
        float2 bv = make_float2(0.f, 0.f);
        if (bias) bv = *(const float2*)(bias + col);
        #pragma unroll
        for (int i = 0; i < 4; i++) {
            int row0 = bm + warp_m * 64 + i * 16 + gr;
            float v00 = acc[i][j][0]*scale + bv.x, v01 = acc[i][j][1]*scale + bv.y;
            float v10 = acc[i][j][2]*scale + bv.x, v11 = acc[i][j][3]*scale + bv.y;
            size_t o0 = (size_t)row0 * ldc + col;
            size_t o1 = (size_t)(row0 + 8) * ldc + col;
            if (Fhi) {
                __half h;
                if (Flo) {
                    h = __float2half(v00); Fhi[o0]   = h; Flo[o0]   = __float2half(v00 - __half2float(h));
                    h = __float2half(v01); Fhi[o0+1] = h; Flo[o0+1] = __float2half(v01 - __half2float(h));
                    h = __float2half(v10); Fhi[o1]   = h; Flo[o1]   = __float2half(v10 - __half2float(h));
                    h = __float2half(v11); Fhi[o1+1] = h; Flo[o1+1] = __float2half(v11 - __half2float(h));
                } else {
                    *(__half2*)(Fhi + o0) = __floats2half2_rn(v00, v01);
                    *(__half2*)(Fhi + o1) = __floats2half2_rn(v10, v11);
                }
            } else {
                *(float2*)(C + o0) = make_float2(v00, v01);
                *(float2*)(C + o1) = make_float2(v10, v11);
            }
        }
    }
}

// ============== fp16 NT GEMM, 1- or 2-term A ==============
#define GF_SMEM (2*3*TILE_E*2)    // 61440 bytes

__global__ __launch_bounds__(256, 2) void gemm_f16_mma(
    const __half* __restrict__ Ahi_, const __half* __restrict__ Alo_,
    const __half* __restrict__ B_,
    const float* __restrict__ bias, float* __restrict__ C_,
    __nv_bfloat16* __restrict__ Chi_, __nv_bfloat16* __restrict__ Clo_,
    int K, int lda, int ldb, int ldc, int nValid, float scale,
    int zmod, long long sA1, long long sA2, long long sB1, long long sB2,
    long long sC1, long long sC2)
{
    extern __shared__ __align__(16) __half smh[];
    const uint32_t smb = smem_u32(smh);

    const int tid = threadIdx.x;
    const int lane = tid & 31;
    const int wid = tid >> 5;
    const int warp_m = wid >> 2;
    const int warp_n = wid & 3;
    const int bm = blockIdx.y * 128;
    const int bn = blockIdx.x * 128;
    const bool two = (Alo_ != nullptr);

    const int z = blockIdx.z;
    const int z1 = z % zmod, z2 = z / zmod;
    const long long offA = (long long)z1 * sA1 + (long long)z2 * sA2;
    const long long offB = (long long)z1 * sB1 + (long long)z2 * sB2;
    const long long offC = (long long)z1 * sC1 + (long long)z2 * sC2;

    const __half* pT[3] = { Ahi_ + offA + (size_t)bm * lda,
                            two ? (Alo_ + offA + (size_t)bm * lda) : nullptr,
                            B_   + offB + (size_t)bn * ldb };

    float acc[4][4][4];
    #pragma unroll
    for (int i = 0; i < 4; i++)
        #pragma unroll
        for (int j = 0; j < 4; j++)
            #pragma unroll
            for (int r = 0; r < 4; r++) acc[i][j][r] = 0.f;

    const int lrow = tid >> 2;
    const int lcol = (tid & 3) * 8;
    const int nstages = K >> 5;

    auto prefetch = [&](int s) {
        const int gk = s * 32;
        const uint32_t base = smb + (uint32_t)((s & 1) * 3 * TILE_E) * 2;
        #pragma unroll
        for (int t = 0; t < 3; t++) {
            if (t == 1 && !two) continue;
            const __half* src = pT[t] + gk + lcol;
            const int ld = (t < 2) ? lda : ldb;
            #pragma unroll
            for (int c = 0; c < 2; c++) {
                int row = lrow + c * 64;
                cp_async16(base + (uint32_t)(t * TILE_E + row * SPAD + lcol) * 2,
                           src + (size_t)row * ld);
            }
        }
    };

    prefetch(0);
    asm volatile("cp.async.commit_group;");

    for (int s = 0; s < nstages; s++) {
        if (s < nstages - 1) {
            prefetch(s + 1);
            asm volatile("cp.async.commit_group;");
            asm volatile("cp.async.wait_group 1;");
        } else {
            asm volatile("cp.async.wait_group 0;");
        }
        __syncthreads();

        const uint32_t stg = smb + (uint32_t)((s & 1) * 3 * TILE_E) * 2;
        const uint32_t tAhi = stg;
        const uint32_t tAlo = stg + TILE_E * 2;
        const uint32_t tB   = stg + 2 * TILE_E * 2;
        const int q  = lane >> 3;
        const int rr = lane & 7;

        #pragma unroll
        for (int ko = 0; ko < 32; ko += 16) {
            const int arow = warp_m * 64 + (q & 1) * 8 + rr;
            const int acol = ko + (q >> 1) * 8;
            const int brow = warp_n * 32 + (q >> 1) * 8 + rr;
            const int bcol = ko + (q & 1) * 8;

            uint32_t b[4][2];
            #pragma unroll
            for (int j = 0; j < 2; j++)
                ldsm_x4(b[2*j][0], b[2*j][1], b[2*j+1][0], b[2*j+1][1],
                        tB + (uint32_t)((brow + j * 16) * SPAD + bcol) * 2);
            uint32_t aH[4][4];
            #pragma unroll
            for (int i = 0; i < 4; i++)
                ldsm_x4(aH[i][0], aH[i][1], aH[i][2], aH[i][3],
                        tAhi + (uint32_t)((arow + i * 16) * SPAD + acol) * 2);
            #pragma unroll
            for (int i = 0; i < 4; i++)
                #pragma unroll
                for (int j = 0; j < 4; j++)
                    mma_f16(acc[i][j], aH[i], b[j]);
            if (two) {
                uint32_t aL[4][4];
                #pragma unroll
                for (int i = 0; i < 4; i++)
                    ldsm_x4(aL[i][0], aL[i][1], aL[i][2], aL[i][3],
                            tAlo + (uint32_t)((arow + i * 16) * SPAD + acol) * 2);
                #pragma unroll
                for (int i = 0; i < 4; i++)
                    #pragma unroll
                    for (int j = 0; j < 4; j++)
                        mma_f16(acc[i][j], aL[i], b[j]);
            }
        }
        __syncthreads();
    }

    const int gr = lane >> 2;
    const int gc = (lane & 3) * 2;
    float* C = C_ ? C_ + offC : nullptr;
    __nv_bfloat16* Chi = Chi_ ? Chi_ + offC : nullptr;
    __nv_bfloat16* Clo = Clo_ ? Clo_ + offC : nullptr;

    #pragma unroll
    for (int j = 0; j < 4; j++) {
        int col = bn + warp_n * 32 + j * 8 + gc;
        if (col >= nValid) continue;
        float2 bv = make_float2(0.f, 0.f);
        if (bias) bv = *(const float2*)(bias + col);
        #pragma unroll
        for (int i = 0; i < 4; i++) {
            int row0 = bm + warp_m * 64 + i * 16 + gr;
            float v00 = acc[i][j][0]*scale + bv.x, v01 = acc[i][j][1]*scale + bv.y;
            float v10 = acc[i][j][2]*scale + bv.x, v11 = acc[i][j][3]*scale + bv.y;
            size_t o0 = (size_t)row0 * ldc + col;
            size_t o1 = (size_t)(row0 + 8) * ldc + col;
            if (Chi) {
                __nv_bfloat16 h;
                h = __float2bfloat16(v00); Chi[o0]   = h; Clo[o0]   = __float2bfloat16(v00 - __bfloat162float(h));
                h = __float2bfloat16(v01); Chi[o0+1] = h; Clo[o0+1] = __float2bfloat16(v01 - __bfloat162float(h));
                h = __float2bfloat16(v10); Chi[o1]   = h; Clo[o1]   = __float2bfloat16(v10 - __bfloat162float(h));
                h = __float2bfloat16(v11); Chi[o1+1] = h; Clo[o1+1] = __float2bfloat16(v11 - __bfloat162float(h));
            } else {
                *(float2*)(C + o0) = make_float2(v00, v01);
                *(float2*)(C + o1) = make_float2(v10, v11);
            }
        }
    }
}

// ---------------- parallel liquid scan (exact affine chunk decomposition) ----------------
__global__ __launch_bounds__(512) void liquid_scan_par(
    const float* __restrict__ I, const float* __restrict__ tau,
    const float* __restrict__ log_dt, float* __restrict__ out) {
    const int b = blockIdx.x;
    const int lg = blockIdx.y;
    const int lane16 = threadIdx.x & 15;
    const int chunk  = threadIdx.x >> 4;
    const int o = lg * 16 + lane16;
    const float dt = expf(log_dt[0]);
    const float r = dt / tau[o];
    const float a = 1.f - r;
    const float* Ib = I + (size_t)b * SS * HH + o;
    const int t0 = chunk * 32;

    float Iv[32];
    #pragma unroll
    for (int i = 0; i < 32; i++) Iv[i] = Ib[(size_t)(t0 + i) * HH];

    float u = 0.f, s = 0.f;
    #pragma unroll
    for (int i = 0; i < 32; i++) {
        float sn = s + r * (u - s);
        u = u + r * (Iv[i] - u);
        s = sn;
    }
    __shared__ float2 dloc[32][16];
    __shared__ float2 st[32][16];
    dloc[chunk][lane16] = make_float2(u, s);
    __syncthreads();

    if (chunk == 0) {
        float a2 = a*a, a4 = a2*a2, a8 = a4*a4, a16 = a8*a8;
        float a32v = a16*a16;
        float a31 = a16*a8*a4*a2*a;
        float c32 = 32.f * r * a31;
        float2 x = make_float2(0.f, 0.f);
        #pragma unroll
        for (int c = 0; c < 32; c++) {
            st[c][lane16] = x;
            float2 d = dloc[c][lane16];
            float nu = a32v * x.x + d.x;
            float ns = c32 * x.x + a32v * x.y + d.y;
            x = make_float2(nu, ns);
        }
    }
    __syncthreads();

    float2 x0 = st[chunk][lane16];
    u = x0.x; s = x0.y;
    float* Ob = out + (size_t)b * SS * HH + o;
    #pragma unroll
    for (int i = 0; i < 32; i++) {
        float sn = s + r * (u - s);
        u = u + r * (Iv[i] - u);
        s = sn;
        Ob[(size_t)(t0 + i) * HH] = tanhf(s);
    }
}

// ---------------- layernorm -> bf16 hi/lo ----------------
__global__ void layernorm_split(const float* __restrict__ in, const float* __restrict__ g,
                                const float* __restrict__ be,
                                __nv_bfloat16* __restrict__ hi, __nv_bfloat16* __restrict__ lo) {
    int row = blockIdx.x;
    int tid = threadIdx.x;
    const float* p = in + (size_t)row * HH;
    float a = p[tid], b = p[tid + 256];
    float sum = a + b, sq = a*a + b*b;
    __shared__ float s1[8], s2[8];
    #pragma unroll
    for (int o = 16; o; o >>= 1) {
        sum += __shfl_xor_sync(0xffffffffu, sum, o);
        sq  += __shfl_xor_sync(0xffffffffu, sq,  o);
    }
    if ((tid & 31) == 0) { s1[tid>>5] = sum; s2[tid>>5] = sq; }
    __syncthreads();
    sum = 0.f; sq = 0.f;
    #pragma unroll
    for (int i = 0; i < 8; i++) { sum += s1[i]; sq += s2[i]; }
    float mean = sum * (1.f/512.f);
    float var  = sq * (1.f/512.f) - mean*mean;
    float inv = rsqrtf(var + 1e-5f);
    float y0 = (a - mean) * inv * g[tid]       + be[tid];
    float y1 = (b - mean) * inv * g[tid + 256] + be[tid + 256];
    size_t base = (size_t)row * HH;
    __nv_bfloat16 h0 = __float2bfloat16(y0);
    __nv_bfloat16 h1 = __float2bfloat16(y1);
    hi[base + tid]       = h0;
    hi[base + tid + 256] = h1;
    lo[base + tid]       = __float2bfloat16(y0 - __bfloat162float(h0));
    lo[base + tid + 256] = __float2bfloat16(y1 - __bfloat162float(h1));
}

// ---------------- qkv split ----------------
__global__ void qkv_split_kernel(const float* __restrict__ qkv) {
    int idx = blockIdx.x * blockDim.x + threadIdx.x;
    if (idx >= MM * 1536) return;
    int row = idx / 1536;
    int col = idx - row * 1536;
    int b = row >> 10, s = row & 1023;
    float v = qkv[idx];
    if (col < 512) {
        int hd = col >> 6, d = col & 63;
        size_t o = ((size_t)(b*8 + hd) * 1024 + s) * 64 + d;
        __nv_bfloat16 h = __float2bfloat16(v);
        g_Qhi[o] = h; g_Qlo[o] = __float2bfloat16(v - __bfloat162float(h));
    } else if (col < 1024) {
        int c = col - 512;
        int hd = c >> 6, d = c & 63;
        size_t o = ((size_t)(b*8 + hd) * 1024 + s) * 64 + d;
        __nv_bfloat16 h = __float2bfloat16(v);
        g_Khi[o] = h; g_Klo[o] = __float2bfloat16(v - __bfloat162float(h));
    } else {
        int c = col - 1024;
        int hd = c >> 6, d = c & 63;
        size_t o = (size_t)(b*8 + hd) * 131072 + (size_t)d * 1024 + s;
        g_Vth[o] = __float2half(v);
    }
}

// ---------------- in-place fp16 softmax over rows of 1024 ----------------
__global__ void softmax_f16_kernel(__half* __restrict__ S) {
    size_t row = blockIdx.x;
    __half* p = S + row * 1024;
    int tid = threadIdx.x;   // 256 threads x 4 halves
    uint2 raw = ((const uint2*)p)[tid];
    __half2 h01 = *(__half2*)&raw.x;
    __half2 h23 = *(__half2*)&raw.y;
    float v0 = __low2float(h01), v1 = __high2float(h01);
    float v2 = __low2float(h23), v3 = __high2float(h23);
    float m = fmaxf(fmaxf(v0, v1), fmaxf(v2, v3));
    __shared__ float red[8];
    #pragma unroll
    for (int o = 16; o; o >>= 1) m = fmaxf(m, __shfl_xor_sync(0xffffffffu, m, o));
    if ((tid & 31) == 0) red[tid>>5] = m;
    __syncthreads();
    m = red[0];
    #pragma unroll
    for (int i = 1; i < 8; i++) m = fmaxf(m, red[i]);
    v0 = __expf(v0 - m); v1 = __expf(v1 - m);
    v2 = __expf(v2 - m); v3 = __expf(v3 - m);
    float sum = v0 + v1 + v2 + v3;
    #pragma unroll
    for (int o = 16; o; o >>= 1) sum += __shfl_xor_sync(0xffffffffu, sum, o);
    __syncthreads();
    if ((tid & 31) == 0) red[tid>>5] = sum;
    __syncthreads();
    sum = 0.f;
    #pragma unroll
    for (int i = 0; i < 8; i++) sum += red[i];
    float inv = 1.f / sum;
    __half2 o01 = __floats2half2_rn(v0 * inv, v1 * inv);
    __half2 o23 = __floats2half2_rn(v2 * inv, v3 * inv);
    uint2 outw;
    outw.x = *(uint32_t*)&o01;
    outw.y = *(uint32_t*)&o23;
    ((uint2*)p)[tid] = outw;
}

// ---------------- host orchestration ----------------
extern "C" void kernel_launch(void* const* d_in, const int* in_sizes, int n_in,
                              void* d_out, int out_size) {
    const int*   x          = (const int*)  d_in[0];
    const float* emb        = (const float*)d_in[1];
    const float* W0         = (const float*)d_in[2];
    const float* b0         = (const float*)d_in[3];
    const float* tau0       = (const float*)d_in[4];
    const float* g0         = (const float*)d_in[5];
    const float* be0        = (const float*)d_in[6];
    const float* W1         = (const float*)d_in[7];
    const float* b1         = (const float*)d_in[8];
    const float* tau1       = (const float*)d_in[9];
    const float* g1         = (const float*)d_in[10];
    const float* be1        = (const float*)d_in[11];
    const float* attn_in_w  = (const float*)d_in[12];
    const float* attn_in_b  = (const float*)d_in[13];
    const float* attn_out_w = (const float*)d_in[14];
    const float* attn_out_b = (const float*)d_in[15];
    const float* out_w      = (const float*)d_in[16];
    const float* out_b      = (const float*)d_in[17];
    const float* log_dt     = (const float*)d_in[18];
    float* out = (float*)d_out;

    float *I, *sbuf, *qkv;
    __nv_bfloat16 *Ahi, *Alo, *A2hi, *A2lo;
    __nv_bfloat16 *W0hi, *W0lo, *W1hi, *W1lo, *Wqhi, *Wqlo, *Wohi, *Wolo;
    __nv_bfloat16 *Qhi, *Qlo, *Khi, *Klo;
    __half *H2hi, *H2lo, *Bh, *Vth, *Sh;
    cudaGetSymbolAddress((void**)&I,      g_I);
    cudaGetSymbolAddress((void**)&sbuf,   g_s);
    cudaGetSymbolAddress((void**)&qkv,    g_qkv);
    cudaGetSymbolAddress((void**)&Ahi,    g_Ahi);
    cudaGetSymbolAddress((void**)&Alo,    g_Alo);
    cudaGetSymbolAddress((void**)&A2hi,   g_A2hi);
    cudaGetSymbolAddress((void**)&A2lo,   g_A2lo);
    cudaGetSymbolAddress((void**)&H2hi,   g_H2hi);
    cudaGetSymbolAddress((void**)&H2lo,   g_H2lo);
    cudaGetSymbolAddress((void**)&Bh,     g_Bh);
    cudaGetSymbolAddress((void**)&W0hi,   g_W0hi);
    cudaGetSymbolAddress((void**)&W0lo,   g_W0lo);
    cudaGetSymbolAddress((void**)&W1hi,   g_W1hi);
    cudaGetSymbolAddress((void**)&W1lo,   g_W1lo);
    cudaGetSymbolAddress((void**)&Wqhi,   g_Wqhi);
    cudaGetSymbolAddress((void**)&Wqlo,   g_Wqlo);
    cudaGetSymbolAddress((void**)&Wohi,   g_Wohi);
    cudaGetSymbolAddress((void**)&Wolo,   g_Wolo);
    cudaGetSymbolAddress((void**)&Qhi,    g_Qhi);
    cudaGetSymbolAddress((void**)&Qlo,    g_Qlo);
    cudaGetSymbolAddress((void**)&Khi,    g_Khi);
    cudaGetSymbolAddress((void**)&Klo,    g_Klo);
    cudaGetSymbolAddress((void**)&Vth,    g_Vth);
    cudaGetSymbolAddress((void**)&Sh,     g_Sh);

    cudaFuncSetAttribute(gemm_pair_mma,
                         cudaFuncAttributeMaxDynamicSharedMemorySize, GP_SMEM);
    cudaFuncSetAttribute(gemm_f16_mma,
                         cudaFuncAttributeMaxDynamicSharedMemorySize, GF_SMEM);

    // weight preprocessing
    convert_f16_kernel<<<(VV*HH + 255)/256, 256>>>(out_w, Bh, VV*HH);
    split_bf16_kernel<<<(HH*EE + 255)/256, 256>>>(W0, W0hi, W0lo, HH*EE);
    split_bf16_kernel<<<(HH*HH + 255)/256, 256>>>(W1, W1hi, W1lo, HH*HH);
    split_bf16_kernel<<<(3*HH*HH + 255)/256, 256>>>(attn_in_w, Wqhi, Wqlo, 3*HH*HH);
    split_bf16_kernel<<<(HH*HH + 255)/256, 256>>>(attn_out_w, Wohi, Wolo, HH*HH);

    // 1. embedding + pos-enc -> bf16 splits
    embed_pe_split<<<(MM*EE)/256, 256>>>(x, emb, Ahi, Alo);

    // 2. liquid layer 0 (bf16 3-term)
    gemm_pair_mma<<<dim3(4, 32, 1), 256, GP_SMEM>>>(
        Ahi, Alo, W0hi, W0lo, b0, I, nullptr, nullptr,
        EE, EE, EE, HH, HH, 1.f, 1, 0,0,0,0,0,0);
    liquid_scan_par<<<dim3(BB, 32), 512>>>(I, tau0, log_dt, sbuf);
    layernorm_split<<<MM, 256>>>(sbuf, g0, be0, Ahi, Alo);

    // 3. liquid layer 1
    gemm_pair_mma<<<dim3(4, 32, 1), 256, GP_SMEM>>>(
        Ahi, Alo, W1hi, W1lo, b1, I, nullptr, nullptr,
        HH, HH, HH, HH, HH, 1.f, 1, 0,0,0,0,0,0);
    liquid_scan_par<<<dim3(BB, 32), 512>>>(I, tau1, log_dt, sbuf);
    layernorm_split<<<MM, 256>>>(sbuf, g1, be1, Ahi, Alo);

    // 4. MHA: qkv projection (bf16 3-term)
    gemm_pair_mma<<<dim3(12, 32, 1), 256, GP_SMEM>>>(
        Ahi, Alo, Wqhi, Wqlo, attn_in_b, qkv, nullptr, nullptr,
        HH, HH, HH, 3*HH, 3*HH, 1.f, 1, 0,0,0,0,0,0);
    qkv_split_kernel<<<(MM*1536 + 255)/256, 256>>>(qkv);

    // scores = Q @ K^T / 8 (bf16 3-term, batched) -> fp16 scores buffer
    gemm_pair_mma<<<dim3(8, 8, 32), 256, GP_SMEM>>>(
        Qhi, Qlo, Khi, Klo, nullptr, nullptr, Sh, nullptr,
        64, 64, 64, 1024, 1024, 0.125f,
        32, 65536LL, 0, 65536LL, 0, 1LL<<20, 0);

    // in-place fp16 softmax -> P
    softmax_f16_kernel<<<32*1024, 256>>>(Sh);

    // AV = P @ Vt^T (fp16 single product) -> fused bf16 split into A2
    gemm_f16_mma<<<dim3(1, 8, 32), 256, GF_SMEM>>>(
        Sh, nullptr, Vth, nullptr, nullptr, A2hi, A2lo,
        1024, 1024, 1024, 512, 64, 1.f,
        8, 1LL<<20, 8LL<<20, 131072LL, 8LL*131072, 64LL, 524288LL);

    // out-projection (bf16 3-term) -> fused fp16 split into H2
    gemm_pair_mma<<<dim3(4, 32, 1), 256, GP_SMEM>>>(
        A2hi, A2lo, Wohi, Wolo, attn_out_b, nullptr, H2hi, H2lo,
        HH, HH, HH, HH, HH, 1.f, 1, 0,0,0,0,0,0);

    // 5. vocab projection (fp16 1-term)
    gemm_f16_mma<<<dim3(VV/128, MM/128, 1), 256, GF_SMEM>>>(
        H2hi, nullptr, Bh, out_b, out, nullptr, nullptr,
        HH, HH, HH, VV, VV, 1.f, 1, 0,0,0,0,0,0);
}

// round 12
// speedup vs baseline: 1.0334x; 1.0334x over previous
#include <cuda_runtime.h>
#include <cuda_bf16.h>
#include <cuda_fp16.h>
#include <cstdint>
#include <math.h>

#define BB 4
#define SS 1024
#define EE 512
#define HH 512
#define VV 32000
#define MM (BB*SS)      // 4096
#define NH 8
#define DH 64

// ---------------- scratch (static device memory; no allocations) ----------------
__device__ float g_I[MM*HH];
__device__ float g_s[MM*HH];
__device__ float g_qkv[MM*3*HH];
__device__ __nv_bfloat16 g_Ahi[MM*HH],  g_Alo[MM*HH];
__device__ __nv_bfloat16 g_A2hi[MM*HH], g_A2lo[MM*HH];
__device__ __half        g_H2hi[MM*HH], g_H2lo[MM*HH];   // h2 fp16 (vocab A)
__device__ __nv_bfloat16 g_W0hi[HH*EE],  g_W0lo[HH*EE];
__device__ __nv_bfloat16 g_W1hi[HH*HH],  g_W1lo[HH*HH];
__device__ __nv_bfloat16 g_Wqhi[3*HH*HH], g_Wqlo[3*HH*HH];
__device__ __nv_bfloat16 g_Wohi[HH*HH],  g_Wolo[HH*HH];
__device__ __half        g_Bh[(size_t)VV*HH];            // vocab weights fp16
__device__ __half        g_Qh[32*1024*64];               // Q fp16 [bh][s][d]
__device__ __half        g_Kh[32*1024*64];               // K fp16 [bh][s][d]
__device__ __half        g_Vth[32*128*1024];             // [bh][d pad128][k]; pad rows stay 0
__device__ __half        g_Sh[(size_t)32*1024*1024];     // scores/P fp16 (in-place)

__device__ __forceinline__ uint32_t smem_u32(const void* p) {
    uint32_t a;
    asm("{ .reg .u64 t; cvta.to.shared.u64 t, %1; cvt.u32.u64 %0, t; }" : "=r"(a) : "l"(p));
    return a;
}
__device__ __forceinline__ void cp_async16(uint32_t dst, const void* src) {
    asm volatile("cp.async.cg.shared.global [%0], [%1], 16;" :: "r"(dst), "l"(src));
}
__device__ __forceinline__ void ldsm_x4(uint32_t& r0, uint32_t& r1, uint32_t& r2, uint32_t& r3,
                                        uint32_t addr) {
    asm volatile("ldmatrix.sync.aligned.m8n8.x4.shared.b16 {%0,%1,%2,%3}, [%4];"
                 : "=r"(r0), "=r"(r1), "=r"(r2), "=r"(r3) : "r"(addr));
}
__device__ __forceinline__ void mma_bf16(float* c, const uint32_t* a, const uint32_t* b) {
    asm volatile("mma.sync.aligned.m16n8k16.row.col.f32.bf16.bf16.f32 "
                 "{%0,%1,%2,%3}, {%4,%5,%6,%7}, {%8,%9}, {%0,%1,%2,%3};"
                 : "+f"(c[0]), "+f"(c[1]), "+f"(c[2]), "+f"(c[3])
                 : "r"(a[0]), "r"(a[1]), "r"(a[2]), "r"(a[3]), "r"(b[0]), "r"(b[1]));
}
__device__ __forceinline__ void mma_f16(float* c, const uint32_t* a, const uint32_t* b) {
    asm volatile("mma.sync.aligned.m16n8k16.row.col.f32.f16.f16.f32 "
                 "{%0,%1,%2,%3}, {%4,%5,%6,%7}, {%8,%9}, {%0,%1,%2,%3};"
                 : "+f"(c[0]), "+f"(c[1]), "+f"(c[2]), "+f"(c[3])
                 : "r"(a[0]), "r"(a[1]), "r"(a[2]), "r"(a[3]), "r"(b[0]), "r"(b[1]));
}

// ---------------- embed + positional encoding -> bf16 hi/lo ----------------
__global__ void embed_pe_split(const int* __restrict__ x, const float* __restrict__ emb,
                               __nv_bfloat16* __restrict__ hi, __nv_bfloat16* __restrict__ lo) {
    int idx = blockIdx.x * blockDim.x + threadIdx.x;
    if (idx >= MM*EE) return;
    int m = idx >> 9;
    int e = idx & 511;
    int s = m & (SS - 1);
    int tok = x[m];
    int i2 = e & ~1;
    float freq = expf((float)i2 * (-9.210340371976184f / 512.0f));
    float ang = (float)s * freq;
    float pe = (e & 1) ? cosf(ang) : sinf(ang);
    float v = emb[(size_t)tok * EE + e] + pe;
    __nv_bfloat16 h = __float2bfloat16(v);
    hi[idx] = h;
    lo[idx] = __float2bfloat16(v - __bfloat162float(h));
}

// ---------------- merged weight preprocessing (1 launch) ----------------
// ranges: [0, VV*HH) vocab->fp16 | then W0, W1, Wq, Wo bf16 hi/lo splits
#define N_VOC (VV*HH)
#define N_W0  (HH*EE)
#define N_W1  (HH*HH)
#define N_WQ  (3*HH*HH)
#define N_WO  (HH*HH)
#define N_PREP (N_VOC + N_W0 + N_W1 + N_WQ + N_WO)

__global__ void weight_prep_kernel(const float* __restrict__ out_w,
                                   const float* __restrict__ W0,
                                   const float* __restrict__ W1,
                                   const float* __restrict__ Wq,
                                   const float* __restrict__ Wo) {
    long long idx = (long long)blockIdx.x * blockDim.x + threadIdx.x;
    if (idx < N_VOC) {
        g_Bh[idx] = __float2half(out_w[idx]);
        return;
    }
    idx -= N_VOC;
    const float* src; __nv_bfloat16 *hi, *lo;
    if (idx < N_W0)       { src = W0; hi = g_W0hi; lo = g_W0lo; }
    else if ((idx -= N_W0) < N_W1) { src = W1; hi = g_W1hi; lo = g_W1lo; }
    else if ((idx -= N_W1) < N_WQ) { src = Wq; hi = g_Wqhi; lo = g_Wqlo; }
    else if ((idx -= N_WQ) < N_WO) { src = Wo; hi = g_Wohi; lo = g_Wolo; }
    else return;
    float v = src[idx];
    __nv_bfloat16 h = __float2bfloat16(v);
    hi[idx] = h;
    lo[idx] = __float2bfloat16(v - __bfloat162float(h));
}

// ============== bf16 3-term paired-operand NT GEMM ==============
#define SPAD 40
#define TILE_E (128*SPAD)
#define GP_SMEM (2*4*TILE_E*2)    // 81920 bytes

__global__ __launch_bounds__(256, 2) void gemm_pair_mma(
    const __nv_bfloat16* __restrict__ Ahi_, const __nv_bfloat16* __restrict__ Alo_,
    const __nv_bfloat16* __restrict__ Bhi_, const __nv_bfloat16* __restrict__ Blo_,
    const float* __restrict__ bias, float* __restrict__ C_,
    __half* __restrict__ Fhi_, __half* __restrict__ Flo_,
    int K, int lda, int ldb, int ldc, int nValid, float scale,
    int zmod, long long sA1, long long sA2, long long sB1, long long sB2,
    long long sC1, long long sC2)
{
    extern __shared__ __align__(16) __nv_bfloat16 sm[];
    const uint32_t smb = smem_u32(sm);

    const int tid = threadIdx.x;
    const int lane = tid & 31;
    const int wid = tid >> 5;
    const int warp_m = wid >> 2;
    const int warp_n = wid & 3;
    const int bm = blockIdx.y * 128;
    const int bn = blockIdx.x * 128;

    const int z = blockIdx.z;
    const int z1 = z % zmod, z2 = z / zmod;
    const long long offA = (long long)z1 * sA1 + (long long)z2 * sA2;
    const long long offB = (long long)z1 * sB1 + (long long)z2 * sB2;
    const long long offC = (long long)z1 * sC1 + (long long)z2 * sC2;

    const __nv_bfloat16* pA[2] = { Ahi_ + offA + (size_t)bm * lda,
                                   Alo_ + offA + (size_t)bm * lda };
    const __nv_bfloat16* pB[2] = { Bhi_ + offB + (size_t)bn * ldb,
                                   Blo_ + offB + (size_t)bn * ldb };

    float acc[4][4][4];
    #pragma unroll
    for (int i = 0; i < 4; i++)
        #pragma unroll
        for (int j = 0; j < 4; j++)
            #pragma unroll
            for (int r = 0; r < 4; r++) acc[i][j][r] = 0.f;

    const int lrow = tid >> 2;
    const int lcol = (tid & 3) * 8;
    const int nstages = K >> 5;

    auto prefetch = [&](int s) {
        const int gk = s * 32;
        const uint32_t base = smb + (uint32_t)((s & 1) * 4 * TILE_E) * 2;
        #pragma unroll
        for (int t = 0; t < 4; t++) {
            const __nv_bfloat16* src = (t < 2 ? pA[t] : pB[t-2]) + gk + lcol;
            const int ld = (t < 2) ? lda : ldb;
            #pragma unroll
            for (int c = 0; c < 2; c++) {
                int row = lrow + c * 64;
                cp_async16(base + (uint32_t)(t * TILE_E + row * SPAD + lcol) * 2,
                           src + (size_t)row * ld);
            }
        }
    };

    prefetch(0);
    asm volatile("cp.async.commit_group;");

    for (int s = 0; s < nstages; s++) {
        if (s < nstages - 1) {
            prefetch(s + 1);
            asm volatile("cp.async.commit_group;");
            asm volatile("cp.async.wait_group 1;");
        } else {
            asm volatile("cp.async.wait_group 0;");
        }
        __syncthreads();

        const uint32_t stg = smb + (uint32_t)((s & 1) * 4 * TILE_E) * 2;
        const uint32_t tAhi = stg;
        const uint32_t tAlo = stg + TILE_E * 2;
        const uint32_t tBhi = stg + 2 * TILE_E * 2;
        const uint32_t tBlo = stg + 3 * TILE_E * 2;
        const int q  = lane >> 3;
        const int rr = lane & 7;

        #pragma unroll
        for (int ko = 0; ko < 32; ko += 16) {
            const int arow = warp_m * 64 + (q & 1) * 8 + rr;
            const int acol = ko + (q >> 1) * 8;
            const int brow = warp_n * 32 + (q >> 1) * 8 + rr;
            const int bcol = ko + (q & 1) * 8;

            uint32_t aH[4][4];
            #pragma unroll
            for (int i = 0; i < 4; i++)
                ldsm_x4(aH[i][0], aH[i][1], aH[i][2], aH[i][3],
                        tAhi + (uint32_t)((arow + i * 16) * SPAD + acol) * 2);
            uint32_t bH[4][2], bL[4][2];
            #pragma unroll
            for (int j = 0; j < 2; j++) {
                ldsm_x4(bH[2*j][0], bH[2*j][1], bH[2*j+1][0], bH[2*j+1][1],
                        tBhi + (uint32_t)((brow + j * 16) * SPAD + bcol) * 2);
                ldsm_x4(bL[2*j][0], bL[2*j][1], bL[2*j+1][0], bL[2*j+1][1],
                        tBlo + (uint32_t)((brow + j * 16) * SPAD + bcol) * 2);
            }
            #pragma unroll
            for (int i = 0; i < 4; i++)
                #pragma unroll
                for (int j = 0; j < 4; j++)
                    mma_bf16(acc[i][j], aH[i], bH[j]);
            #pragma unroll
            for (int i = 0; i < 4; i++)
                #pragma unroll
                for (int j = 0; j < 4; j++)
                    mma_bf16(acc[i][j], aH[i], bL[j]);
            uint32_t aL[4][4];
            #pragma unroll
            for (int i = 0; i < 4; i++)
                ldsm_x4(aL[i][0], aL[i][1], aL[i][2], aL[i][3],
                        tAlo + (uint32_t)((arow + i * 16) * SPAD + acol) * 2);
            #pragma unroll
            for (int i = 0; i < 4; i++)
                #pragma unroll
                for (int j = 0; j < 4; j++)
                    mma_bf16(acc[i][j], aL[i], bH[j]);
        }
        __syncthreads();
    }

    // epilogue: fp32, fp16 hi/lo split, or single fp16
    const int gr = lane >> 2;
    const int gc = (lane & 3) * 2;
    float* C = C_ ? C_ + offC : nullptr;
    __half* Fhi = Fhi_ ? Fhi_ + offC : nullptr;
    __half* Flo = Flo_ ? Flo_ + offC : nullptr;

    #pragma unroll
    for (int j = 0; j < 4; j++) {
        int col = bn + warp_n * 32 + j * 8 + gc;
        if (col >= nValid) continue;
        float2 bv = make_float2(0.f, 0.f);
        if (bias) bv = *(const float2*)(bias + col);
        #pragma unroll
        for (int i = 0; i < 4; i++) {
            int row0 = bm + warp_m * 64 + i * 16 + gr;
            float v00 = acc[i][j][0]*scale + bv.x, v01 = acc[i][j][1]*scale + bv.y;
            float v10 = acc[i][j][2]*scale + bv.x, v11 = acc[i][j][3]*scale + bv.y;
            size_t o0 = (size_t)row0 * ldc + col;
            size_t o1 = (size_t)(row0 + 8) * ldc + col;
            if (Fhi) {
                __half h;
                if (Flo) {
                    h = __float2half(v00); Fhi[o0]   = h; Flo[o0]   = __float2half(v00 - __half2float(h));
                    h = __float2half(v01); Fhi[o0+1] = h; Flo[o0+1] = __float2half(v01 - __half2float(h));
                    h = __float2half(v10); Fhi[o1]   = h; Flo[o1]   = __float2half(v10 - __half2float(h));
                    h = __float2half(v11); Fhi[o1+1] = h; Flo[o1+1] = __float2half(v11 - __half2float(h));
                } else {
                    *(__half2*)(Fhi + o0) = __floats2half2_rn(v00, v01);
                    *(__half2*)(Fhi + o1) = __floats2half2_rn(v10, v11);
                }
            } else {
                *(float2*)(C + o0) = make_float2(v00, v01);
                *(float2*)(C + o1) = make_float2(v10, v11);
            }
        }
    }
}

// ============== fp16 NT GEMM, 1- or 2-term A ==============
// outputs: fp32 C_, bf16 split (Chi_/Clo_), or single fp16 Fh_
#define GF_SMEM (2*3*TILE_E*2)    // 61440 bytes

__global__ __launch_bounds__(256, 2) void gemm_f16_mma(
    const __half* __restrict__ Ahi_, const __half* __restrict__ Alo_,
    const __half* __restrict__ B_,
    const float* __restrict__ bias, float* __restrict__ C_,
    __nv_bfloat16* __restrict__ Chi_, __nv_bfloat16* __restrict__ Clo_,
    __half* __restrict__ Fh_,
    int K, int lda, int ldb, int ldc, int nValid, float scale,
    int zmod, long long sA1, long long sA2, long long sB1, long long sB2,
    long long sC1, long long sC2)
{
    extern __shared__ __align__(16) __half smh[];
    const uint32_t smb = smem_u32(smh);

    const int tid = threadIdx.x;
    const int lane = tid & 31;
    const int wid = tid >> 5;
    const int warp_m = wid >> 2;
    const int warp_n = wid & 3;
    const int bm = blockIdx.y * 128;
    const int bn = blockIdx.x * 128;
    const bool two = (Alo_ != nullptr);

    const int z = blockIdx.z;
    const int z1 = z % zmod, z2 = z / zmod;
    const long long offA = (long long)z1 * sA1 + (long long)z2 * sA2;
    const long long offB = (long long)z1 * sB1 + (long long)z2 * sB2;
    const long long offC = (long long)z1 * sC1 + (long long)z2 * sC2;

    const __half* pT[3] = { Ahi_ + offA + (size_t)bm * lda,
                            two ? (Alo_ + offA + (size_t)bm * lda) : nullptr,
                            B_   + offB + (size_t)bn * ldb };

    float acc[4][4][4];
    #pragma unroll
    for (int i = 0; i < 4; i++)
        #pragma unroll
        for (int j = 0; j < 4; j++)
            #pragma unroll
            for (int r = 0; r < 4; r++) acc[i][j][r] = 0.f;

    const int lrow = tid >> 2;
    const int lcol = (tid & 3) * 8;
    const int nstages = K >> 5;

    auto prefetch = [&](int s) {
        const int gk = s * 32;
        const uint32_t base = smb + (uint32_t)((s & 1) * 3 * TILE_E) * 2;
        #pragma unroll
        for (int t = 0; t < 3; t++) {
            if (t == 1 && !two) continue;
            const __half* src = pT[t] + gk + lcol;
            const int ld = (t < 2) ? lda : ldb;
            #pragma unroll
            for (int c = 0; c < 2; c++) {
                int row = lrow + c * 64;
                cp_async16(base + (uint32_t)(t * TILE_E + row * SPAD + lcol) * 2,
                           src + (size_t)row * ld);
            }
        }
    };

    prefetch(0);
    asm volatile("cp.async.commit_group;");

    for (int s = 0; s < nstages; s++) {
        if (s < nstages - 1) {
            prefetch(s + 1);
            asm volatile("cp.async.commit_group;");
            asm volatile("cp.async.wait_group 1;");
        } else {
            asm volatile("cp.async.wait_group 0;");
        }
        __syncthreads();

        const uint32_t stg = smb + (uint32_t)((s & 1) * 3 * TILE_E) * 2;
        const uint32_t tAhi = stg;
        const uint32_t tAlo = stg + TILE_E * 2;
        const uint32_t tB   = stg + 2 * TILE_E * 2;
        const int q  = lane >> 3;
        const int rr = lane & 7;

        #pragma unroll
        for (int ko = 0; ko < 32; ko += 16) {
            const int arow = warp_m * 64 + (q & 1) * 8 + rr;
            const int acol = ko + (q >> 1) * 8;
            const int brow = warp_n * 32 + (q >> 1) * 8 + rr;
            const int bcol = ko + (q & 1) * 8;

            uint32_t b[4][2];
            #pragma unroll
            for (int j = 0; j < 2; j++)
                ldsm_x4(b[2*j][0], b[2*j][1], b[2*j+1][0], b[2*j+1][1],
                        tB + (uint32_t)((brow + j * 16) * SPAD + bcol) * 2);
            uint32_t aH[4][4];
            #pragma unroll
            for (int i = 0; i < 4; i++)
                ldsm_x4(aH[i][0], aH[i][1], aH[i][2], aH[i][3],
                        tAhi + (uint32_t)((arow + i * 16) * SPAD + acol) * 2);
            #pragma unroll
            for (int i = 0; i < 4; i++)
                #pragma unroll
                for (int j = 0; j < 4; j++)
                    mma_f16(acc[i][j], aH[i], b[j]);
            if (two) {
                uint32_t aL[4][4];
                #pragma unroll
                for (int i = 0; i < 4; i++)
                    ldsm_x4(aL[i][0], aL[i][1], aL[i][2], aL[i][3],
                            tAlo + (uint32_t)((arow + i * 16) * SPAD + acol) * 2);
                #pragma unroll
                for (int i = 0; i < 4; i++)
                    #pragma unroll
                    for (int j = 0; j < 4; j++)
                        mma_f16(acc[i][j], aL[i], b[j]);
            }
        }
        __syncthreads();
    }

    const int gr = lane >> 2;
    const int gc = (lane & 3) * 2;
    float* C = C_ ? C_ + offC : nullptr;
    __nv_bfloat16* Chi = Chi_ ? Chi_ + offC : nullptr;
    __nv_bfloat16* Clo = Clo_ ? Clo_ + offC : nullptr;
    __half* Fh = Fh_ ? Fh_ + offC : nullptr;

    #pragma unroll
    for (int j = 0; j < 4; j++) {
        int col = bn + warp_n * 32 + j * 8 + gc;
        if (col >= nValid) continue;
        float2 bv = make_float2(0.f, 0.f);
        if (bias) bv = *(const float2*)(bias + col);
        #pragma unroll
        for (int i = 0; i < 4; i++) {
            int row0 = bm + warp_m * 64 + i * 16 + gr;
            float v00 = acc[i][j][0]*scale + bv.x, v01 = acc[i][j][1]*scale + bv.y;
            float v10 = acc[i][j][2]*scale + bv.x, v11 = acc[i][j][3]*scale + bv.y;
            size_t o0 = (size_t)row0 * ldc + col;
            size_t o1 = (size_t)(row0 + 8) * ldc + col;
            if (Chi) {
                __nv_bfloat16 h;
                h = __float2bfloat16(v00); Chi[o0]   = h; Clo[o0]   = __float2bfloat16(v00 - __bfloat162float(h));
                h = __float2bfloat16(v01); Chi[o0+1] = h; Clo[o0+1] = __float2bfloat16(v01 - __bfloat162float(h));
                h = __float2bfloat16(v10); Chi[o1]   = h; Clo[o1]   = __float2bfloat16(v10 - __bfloat162float(h));
                h = __float2bfloat16(v11); Chi[o1+1] = h; Clo[o1+1] = __float2bfloat16(v11 - __bfloat162float(h));
            } else if (Fh) {
                *(__half2*)(Fh + o0) = __floats2half2_rn(v00, v01);
                *(__half2*)(Fh + o1) = __floats2half2_rn(v10, v11);
            } else {
                *(float2*)(C + o0) = make_float2(v00, v01);
                *(float2*)(C + o1) = make_float2(v10, v11);
            }
        }
    }
}

// ---------------- parallel liquid scan (exact affine chunk decomposition) ----------------
__global__ __launch_bounds__(512) void liquid_scan_par(
    const float* __restrict__ I, const float* __restrict__ tau,
    const float* __restrict__ log_dt, float* __restrict__ out) {
    const int b = blockIdx.x;
    const int lg = blockIdx.y;
    const int lane16 = threadIdx.x & 15;
    const int chunk  = threadIdx.x >> 4;
    const int o = lg * 16 + lane16;
    const float dt = expf(log_dt[0]);
    const float r = dt / tau[o];
    const float a = 1.f - r;
    const float* Ib = I + (size_t)b * SS * HH + o;
    const int t0 = chunk * 32;

    float Iv[32];
    #pragma unroll
    for (int i = 0; i < 32; i++) Iv[i] = Ib[(size_t)(t0 + i) * HH];

    float u = 0.f, s = 0.f;
    #pragma unroll
    for (int i = 0; i < 32; i++) {
        float sn = s + r * (u - s);
        u = u + r * (Iv[i] - u);
        s = sn;
    }
    __shared__ float2 dloc[32][16];
    __shared__ float2 st[32][16];
    dloc[chunk][lane16] = make_float2(u, s);
    __syncthreads();

    if (chunk == 0) {
        float a2 = a*a, a4 = a2*a2, a8 = a4*a4, a16 = a8*a8;
        float a32v = a16*a16;
        float a31 = a16*a8*a4*a2*a;
        float c32 = 32.f * r * a31;
        float2 x = make_float2(0.f, 0.f);
        #pragma unroll
        for (int c = 0; c < 32; c++) {
            st[c][lane16] = x;
            float2 d = dloc[c][lane16];
            float nu = a32v * x.x + d.x;
            float ns = c32 * x.x + a32v * x.y + d.y;
            x = make_float2(nu, ns);
        }
    }
    __syncthreads();

    float2 x0 = st[chunk][lane16];
    u = x0.x; s = x0.y;
    float* Ob = out + (size_t)b * SS * HH + o;
    #pragma unroll
    for (int i = 0; i < 32; i++) {
        float sn = s + r * (u - s);
        u = u + r * (Iv[i] - u);
        s = sn;
        Ob[(size_t)(t0 + i) * HH] = tanhf(s);
    }
}

// ---------------- layernorm -> bf16 hi/lo ----------------
__global__ void layernorm_split(const float* __restrict__ in, const float* __restrict__ g,
                                const float* __restrict__ be,
                                __nv_bfloat16* __restrict__ hi, __nv_bfloat16* __restrict__ lo) {
    int row = blockIdx.x;
    int tid = threadIdx.x;
    const float* p = in + (size_t)row * HH;
    float a = p[tid], b = p[tid + 256];
    float sum = a + b, sq = a*a + b*b;
    __shared__ float s1[8], s2[8];
    #pragma unroll
    for (int o = 16; o; o >>= 1) {
        sum += __shfl_xor_sync(0xffffffffu, sum, o);
        sq  += __shfl_xor_sync(0xffffffffu, sq,  o);
    }
    if ((tid & 31) == 0) { s1[tid>>5] = sum; s2[tid>>5] = sq; }
    __syncthreads();
    sum = 0.f; sq = 0.f;
    #pragma unroll
    for (int i = 0; i < 8; i++) { sum += s1[i]; sq += s2[i]; }
    float mean = sum * (1.f/512.f);
    float var  = sq * (1.f/512.f) - mean*mean;
    float inv = rsqrtf(var + 1e-5f);
    float y0 = (a - mean) * inv * g[tid]       + be[tid];
    float y1 = (b - mean) * inv * g[tid + 256] + be[tid + 256];
    size_t base = (size_t)row * HH;
    __nv_bfloat16 h0 = __float2bfloat16(y0);
    __nv_bfloat16 h1 = __float2bfloat16(y1);
    hi[base + tid]       = h0;
    hi[base + tid + 256] = h1;
    lo[base + tid]       = __float2bfloat16(y0 - __bfloat162float(h0));
    lo[base + tid + 256] = __float2bfloat16(y1 - __bfloat162float(h1));
}

// ---------------- qkv split: Q/K fp16 [bh][s][d], V fp16 transposed [bh][d pad128][k] ----------------
__global__ void qkv_split_kernel(const float* __restrict__ qkv) {
    int idx = blockIdx.x * blockDim.x + threadIdx.x;
    if (idx >= MM * 1536) return;
    int row = idx / 1536;
    int col = idx - row * 1536;
    int b = row >> 10, s = row & 1023;
    float v = qkv[idx];
    if (col < 512) {
        int hd = col >> 6, d = col & 63;
        g_Qh[((size_t)(b*8 + hd) * 1024 + s) * 64 + d] = __float2half(v);
    } else if (col < 1024) {
        int c = col - 512;
        int hd = c >> 6, d = c & 63;
        g_Kh[((size_t)(b*8 + hd) * 1024 + s) * 64 + d] = __float2half(v);
    } else {
        int c = col - 1024;
        int hd = c >> 6, d = c & 63;
        g_Vth[(size_t)(b*8 + hd) * 131072 + (size_t)d * 1024 + s] = __float2half(v);
    }
}

// ---------------- in-place fp16 softmax over rows of 1024 ----------------
__global__ void softmax_f16_kernel(__half* __restrict__ S) {
    size_t row = blockIdx.x;
    __half* p = S + row * 1024;
    int tid = threadIdx.x;   // 256 threads x 4 halves
    uint2 raw = ((const uint2*)p)[tid];
    __half2 h01 = *(__half2*)&raw.x;
    __half2 h23 = *(__half2*)&raw.y;
    float v0 = __low2float(h01), v1 = __high2float(h01);
    float v2 = __low2float(h23), v3 = __high2float(h23);
    float m = fmaxf(fmaxf(v0, v1), fmaxf(v2, v3));
    __shared__ float red[8];
    #pragma unroll
    for (int o = 16; o; o >>= 1) m = fmaxf(m, __shfl_xor_sync(0xffffffffu, m, o));
    if ((tid & 31) == 0) red[tid>>5] = m;
    __syncthreads();
    m = red[0];
    #pragma unroll
    for (int i = 1; i < 8; i++) m = fmaxf(m, red[i]);
    v0 = __expf(v0 - m); v1 = __expf(v1 - m);
    v2 = __expf(v2 - m); v3 = __expf(v3 - m);
    float sum = v0 + v1 + v2 + v3;
    #pragma unroll
    for (int o = 16; o; o >>= 1) sum += __shfl_xor_sync(0xffffffffu, sum, o);
    __syncthreads();
    if ((tid & 31) == 0) red[tid>>5] = sum;
    __syncthreads();
    sum = 0.f;
    #pragma unroll
    for (int i = 0; i < 8; i++) sum += red[i];
    float inv = 1.f / sum;
    __half2 o01 = __floats2half2_rn(v0 * inv, v1 * inv);
    __half2 o23 = __floats2half2_rn(v2 * inv, v3 * inv);
    uint2 outw;
    outw.x = *(uint32_t*)&o01;
    outw.y = *(uint32_t*)&o23;
    ((uint2*)p)[tid] = outw;
}

// ---------------- host orchestration ----------------
extern "C" void kernel_launch(void* const* d_in, const int* in_sizes, int n_in,
                              void* d_out, int out_size) {
    const int*   x          = (const int*)  d_in[0];
    const float* emb        = (const float*)d_in[1];
    const float* W0         = (const float*)d_in[2];
    const float* b0         = (const float*)d_in[3];
    const float* tau0       = (const float*)d_in[4];
    const float* g0         = (const float*)d_in[5];
    const float* be0        = (const float*)d_in[6];
    const float* W1         = (const float*)d_in[7];
    const float* b1         = (const float*)d_in[8];
    const float* tau1       = (const float*)d_in[9];
    const float* g1         = (const float*)d_in[10];
    const float* be1        = (const float*)d_in[11];
    const float* attn_in_w  = (const float*)d_in[12];
    const float* attn_in_b  = (const float*)d_in[13];
    const float* attn_out_w = (const float*)d_in[14];
    const float* attn_out_b = (const float*)d_in[15];
    const float* out_w      = (const float*)d_in[16];
    const float* out_b      = (const float*)d_in[17];
    const float* log_dt     = (const float*)d_in[18];
    float* out = (float*)d_out;

    float *I, *sbuf, *qkv;
    __nv_bfloat16 *Ahi, *Alo, *A2hi, *A2lo;
    __nv_bfloat16 *W0hi, *W0lo, *W1hi, *W1lo, *Wqhi, *Wqlo, *Wohi, *Wolo;
    __half *H2hi, *H2lo, *Bh, *Qh, *Kh, *Vth, *Sh;
    cudaGetSymbolAddress((void**)&I,      g_I);
    cudaGetSymbolAddress((void**)&sbuf,   g_s);
    cudaGetSymbolAddress((void**)&qkv,    g_qkv);
    cudaGetSymbolAddress((void**)&Ahi,    g_Ahi);
    cudaGetSymbolAddress((void**)&Alo,    g_Alo);
    cudaGetSymbolAddress((void**)&A2hi,   g_A2hi);
    cudaGetSymbolAddress((void**)&A2lo,   g_A2lo);
    cudaGetSymbolAddress((void**)&H2hi,   g_H2hi);
    cudaGetSymbolAddress((void**)&H2lo,   g_H2lo);
    cudaGetSymbolAddress((void**)&Bh,     g_Bh);
    cudaGetSymbolAddress((void**)&W0hi,   g_W0hi);
    cudaGetSymbolAddress((void**)&W0lo,   g_W0lo);
    cudaGetSymbolAddress((void**)&W1hi,   g_W1hi);
    cudaGetSymbolAddress((void**)&W1lo,   g_W1lo);
    cudaGetSymbolAddress((void**)&Wqhi,   g_Wqhi);
    cudaGetSymbolAddress((void**)&Wqlo,   g_Wqlo);
    cudaGetSymbolAddress((void**)&Wohi,   g_Wohi);
    cudaGetSymbolAddress((void**)&Wolo,   g_Wolo);
    cudaGetSymbolAddress((void**)&Qh,     g_Qh);
    cudaGetSymbolAddress((void**)&Kh,     g_Kh);
    cudaGetSymbolAddress((void**)&Vth,    g_Vth);
    cudaGetSymbolAddress((void**)&Sh,     g_Sh);

    cudaFuncSetAttribute(gemm_pair_mma,
                         cudaFuncAttributeMaxDynamicSharedMemorySize, GP_SMEM);
    cudaFuncSetAttribute(gemm_f16_mma,
                         cudaFuncAttributeMaxDynamicSharedMemorySize, GF_SMEM);

    // weight preprocessing (single merged launch)
    weight_prep_kernel<<<(N_PREP + 255)/256, 256>>>(out_w, W0, W1, attn_in_w, attn_out_w);

    // 1. embedding + pos-enc -> bf16 splits
    embed_pe_split<<<(MM*EE)/256, 256>>>(x, emb, Ahi, Alo);

    // 2. liquid layer 0 (bf16 3-term)
    gemm_pair_mma<<<dim3(4, 32, 1), 256, GP_SMEM>>>(
        Ahi, Alo, W0hi, W0lo, b0, I, nullptr, nullptr,
        EE, EE, EE, HH, HH, 1.f, 1, 0,0,0,0,0,0);
    liquid_scan_par<<<dim3(BB, 32), 512>>>(I, tau0, log_dt, sbuf);
    layernorm_split<<<MM, 256>>>(sbuf, g0, be0, Ahi, Alo);

    // 3. liquid layer 1
    gemm_pair_mma<<<dim3(4, 32, 1), 256, GP_SMEM>>>(
        Ahi, Alo, W1hi, W1lo, b1, I, nullptr, nullptr,
        HH, HH, HH, HH, HH, 1.f, 1, 0,0,0,0,0,0);
    liquid_scan_par<<<dim3(BB, 32), 512>>>(I, tau1, log_dt, sbuf);
    layernorm_split<<<MM, 256>>>(sbuf, g1, be1, Ahi, Alo);

    // 4. MHA: qkv projection (bf16 3-term)
    gemm_pair_mma<<<dim3(12, 32, 1), 256, GP_SMEM>>>(
        Ahi, Alo, Wqhi, Wqlo, attn_in_b, qkv, nullptr, nullptr,
        HH, HH, HH, 3*HH, 3*HH, 1.f, 1, 0,0,0,0,0,0);
    qkv_split_kernel<<<(MM*1536 + 255)/256, 256>>>(qkv);

    // scores = Q @ K^T / 8 (fp16 single-product, batched) -> fp16 scores
    gemm_f16_mma<<<dim3(8, 8, 32), 256, GF_SMEM>>>(
        Qh, nullptr, Kh, nullptr, nullptr, nullptr, nullptr, Sh,
        64, 64, 64, 1024, 1024, 0.125f,
        32, 65536LL, 0, 65536LL, 0, 1LL<<20, 0);

    // in-place fp16 softmax -> P
    softmax_f16_kernel<<<32*1024, 256>>>(Sh);

    // AV = P @ Vt^T (fp16 single product) -> fused bf16 split into A2
    gemm_f16_mma<<<dim3(1, 8, 32), 256, GF_SMEM>>>(
        Sh, nullptr, Vth, nullptr, nullptr, A2hi, A2lo, nullptr,
        1024, 1024, 1024, 512, 64, 1.f,
        8, 1LL<<20, 8LL<<20, 131072LL, 8LL*131072, 64LL, 524288LL);

    // out-projection (bf16 3-term) -> fused fp16 split into H2
    gemm_pair_mma<<<dim3(4, 32, 1), 256, GP_SMEM>>>(
        A2hi, A2lo, Wohi, Wolo, attn_out_b, nullptr, H2hi, H2lo,
        HH, HH, HH, HH, HH, 1.f, 1, 0,0,0,0,0,0);

    // 5. vocab projection (fp16 1-term)
    gemm_f16_mma<<<dim3(VV/128, MM/128, 1), 256, GF_SMEM>>>(
        H2hi, nullptr, Bh, out_b, out, nullptr, nullptr, nullptr,
        HH, HH, HH, VV, VV, 1.f, 1, 0,0,0,0,0,0);
}

// round 13
// speedup vs baseline: 1.0927x; 1.0574x over previous
#include <cuda_runtime.h>
#include <cuda_bf16.h>
#include <cuda_fp16.h>
#include <cstdint>
#include <math.h>

#define BB 4
#define SS 1024
#define EE 512
#define HH 512
#define VV 32000
#define MM (BB*SS)      // 4096
#define NH 8
#define DH 64

// ---------------- scratch (static device memory; no allocations) ----------------
__device__ float g_I[MM*HH];
__device__ float g_s[MM*HH];
__device__ float g_qkv[MM*3*HH];
__device__ __half g_Ahi[MM*HH],  g_Alo[MM*HH];    // activation fp16 hi/lo
__device__ __half g_A2hi[MM*HH], g_A2lo[MM*HH];   // attention-out fp16 hi/lo
__device__ __half g_H2[MM*HH];                    // h2 fp16 (vocab A)
__device__ __half g_W0h[HH*EE];
__device__ __half g_W1h[HH*HH];
__device__ __half g_Wqh[3*HH*HH];
__device__ __half g_Woh[HH*HH];
__device__ __half g_Bh[(size_t)VV*HH];            // vocab weights fp16
__device__ __half g_Qh[32*1024*64];               // Q fp16 [bh][s][d]
__device__ __half g_Kh[32*1024*64];               // K fp16 [bh][s][d]
__device__ __half g_Vth[32*128*1024];             // [bh][d pad128][k]; pad rows stay 0
__device__ __half g_Sh[(size_t)32*1024*1024];     // scores/P fp16 (in-place)

__device__ __forceinline__ uint32_t smem_u32(const void* p) {
    uint32_t a;
    asm("{ .reg .u64 t; cvta.to.shared.u64 t, %1; cvt.u32.u64 %0, t; }" : "=r"(a) : "l"(p));
    return a;
}
__device__ __forceinline__ void cp_async16(uint32_t dst, const void* src) {
    asm volatile("cp.async.cg.shared.global [%0], [%1], 16;" :: "r"(dst), "l"(src));
}
__device__ __forceinline__ void ldsm_x4(uint32_t& r0, uint32_t& r1, uint32_t& r2, uint32_t& r3,
                                        uint32_t addr) {
    asm volatile("ldmatrix.sync.aligned.m8n8.x4.shared.b16 {%0,%1,%2,%3}, [%4];"
                 : "=r"(r0), "=r"(r1), "=r"(r2), "=r"(r3) : "r"(addr));
}
__device__ __forceinline__ void mma_f16(float* c, const uint32_t* a, const uint32_t* b) {
    asm volatile("mma.sync.aligned.m16n8k16.row.col.f32.f16.f16.f32 "
                 "{%0,%1,%2,%3}, {%4,%5,%6,%7}, {%8,%9}, {%0,%1,%2,%3};"
                 : "+f"(c[0]), "+f"(c[1]), "+f"(c[2]), "+f"(c[3])
                 : "r"(a[0]), "r"(a[1]), "r"(a[2]), "r"(a[3]), "r"(b[0]), "r"(b[1]));
}

// ---------------- merged preprocessing: vocab/W converts + embed+PE split (1 launch) ----------------
#define N_VOC ((long long)VV*HH)
#define N_W0  (HH*EE)
#define N_W1  (HH*HH)
#define N_WQ  (3*HH*HH)
#define N_WO  (HH*HH)
#define N_EMB (MM*EE)
#define N_PREP (N_VOC + N_W0 + N_W1 + N_WQ + N_WO + N_EMB)

__global__ void prep_kernel(const float* __restrict__ out_w,
                            const float* __restrict__ W0,
                            const float* __restrict__ W1,
                            const float* __restrict__ Wq,
                            const float* __restrict__ Wo,
                            const int* __restrict__ x,
                            const float* __restrict__ emb) {
    long long idx = (long long)blockIdx.x * blockDim.x + threadIdx.x;
    if (idx < N_VOC) { g_Bh[idx] = __float2half(out_w[idx]); return; }
    idx -= N_VOC;
    if (idx < N_W0) { g_W0h[idx] = __float2half(W0[idx]); return; }
    idx -= N_W0;
    if (idx < N_W1) { g_W1h[idx] = __float2half(W1[idx]); return; }
    idx -= N_W1;
    if (idx < N_WQ) { g_Wqh[idx] = __float2half(Wq[idx]); return; }
    idx -= N_WQ;
    if (idx < N_WO) { g_Woh[idx] = __float2half(Wo[idx]); return; }
    idx -= N_WO;
    if (idx >= N_EMB) return;
    // embed + positional encoding -> fp16 hi/lo
    int i = (int)idx;
    int m = i >> 9;
    int e = i & 511;
    int s = m & (SS - 1);
    int tok = x[m];
    int i2 = e & ~1;
    float freq = expf((float)i2 * (-9.210340371976184f / 512.0f));
    float ang = (float)s * freq;
    float pe = (e & 1) ? cosf(ang) : sinf(ang);
    float v = emb[(size_t)tok * EE + e] + pe;
    __half h = __float2half(v);
    g_Ahi[i] = h;
    g_Alo[i] = __float2half(v - __half2float(h));
}

// ============== fp16 NT GEMM, 1- or 2-term A: C = scale*((Ahi[+Alo])@B^T)+bias ==============
// outputs: fp32 C_, fp16 hi/lo split (Chi_/Clo_), or single fp16 Fh_
#define SPAD 40
#define TILE_E (128*SPAD)
#define GF_SMEM (2*3*TILE_E*2)    // 61440 bytes

__global__ __launch_bounds__(256, 2) void gemm_f16_mma(
    const __half* __restrict__ Ahi_, const __half* __restrict__ Alo_,
    const __half* __restrict__ B_,
    const float* __restrict__ bias, float* __restrict__ C_,
    __half* __restrict__ Chi_, __half* __restrict__ Clo_,
    __half* __restrict__ Fh_,
    int K, int lda, int ldb, int ldc, int nValid, float scale,
    int zmod, long long sA1, long long sA2, long long sB1, long long sB2,
    long long sC1, long long sC2)
{
    extern __shared__ __align__(16) __half smh[];
    const uint32_t smb = smem_u32(smh);

    const int tid = threadIdx.x;
    const int lane = tid & 31;
    const int wid = tid >> 5;
    const int warp_m = wid >> 2;
    const int warp_n = wid & 3;
    const int bm = blockIdx.y * 128;
    const int bn = blockIdx.x * 128;
    const bool two = (Alo_ != nullptr);

    const int z = blockIdx.z;
    const int z1 = z % zmod, z2 = z / zmod;
    const long long offA = (long long)z1 * sA1 + (long long)z2 * sA2;
    const long long offB = (long long)z1 * sB1 + (long long)z2 * sB2;
    const long long offC = (long long)z1 * sC1 + (long long)z2 * sC2;

    const __half* pT[3] = { Ahi_ + offA + (size_t)bm * lda,
                            two ? (Alo_ + offA + (size_t)bm * lda) : nullptr,
                            B_   + offB + (size_t)bn * ldb };

    float acc[4][4][4];
    #pragma unroll
    for (int i = 0; i < 4; i++)
        #pragma unroll
        for (int j = 0; j < 4; j++)
            #pragma unroll
            for (int r = 0; r < 4; r++) acc[i][j][r] = 0.f;

    const int lrow = tid >> 2;
    const int lcol = (tid & 3) * 8;
    const int nstages = K >> 5;

    auto prefetch = [&](int s) {
        const int gk = s * 32;
        const uint32_t base = smb + (uint32_t)((s & 1) * 3 * TILE_E) * 2;
        #pragma unroll
        for (int t = 0; t < 3; t++) {
            if (t == 1 && !two) continue;
            const __half* src = pT[t] + gk + lcol;
            const int ld = (t < 2) ? lda : ldb;
            #pragma unroll
            for (int c = 0; c < 2; c++) {
                int row = lrow + c * 64;
                cp_async16(base + (uint32_t)(t * TILE_E + row * SPAD + lcol) * 2,
                           src + (size_t)row * ld);
            }
        }
    };

    prefetch(0);
    asm volatile("cp.async.commit_group;");

    for (int s = 0; s < nstages; s++) {
        if (s < nstages - 1) {
            prefetch(s + 1);
            asm volatile("cp.async.commit_group;");
            asm volatile("cp.async.wait_group 1;");
        } else {
            asm volatile("cp.async.wait_group 0;");
        }
        __syncthreads();

        const uint32_t stg = smb + (uint32_t)((s & 1) * 3 * TILE_E) * 2;
        const uint32_t tAhi = stg;
        const uint32_t tAlo = stg + TILE_E * 2;
        const uint32_t tB   = stg + 2 * TILE_E * 2;
        const int q  = lane >> 3;
        const int rr = lane & 7;

        #pragma unroll
        for (int ko = 0; ko < 32; ko += 16) {
            const int arow = warp_m * 64 + (q & 1) * 8 + rr;
            const int acol = ko + (q >> 1) * 8;
            const int brow = warp_n * 32 + (q >> 1) * 8 + rr;
            const int bcol = ko + (q & 1) * 8;

            uint32_t b[4][2];
            #pragma unroll
            for (int j = 0; j < 2; j++)
                ldsm_x4(b[2*j][0], b[2*j][1], b[2*j+1][0], b[2*j+1][1],
                        tB + (uint32_t)((brow + j * 16) * SPAD + bcol) * 2);
            uint32_t aH[4][4];
            #pragma unroll
            for (int i = 0; i < 4; i++)
                ldsm_x4(aH[i][0], aH[i][1], aH[i][2], aH[i][3],
                        tAhi + (uint32_t)((arow + i * 16) * SPAD + acol) * 2);
            #pragma unroll
            for (int i = 0; i < 4; i++)
                #pragma unroll
                for (int j = 0; j < 4; j++)
                    mma_f16(acc[i][j], aH[i], b[j]);
            if (two) {
                uint32_t aL[4][4];
                #pragma unroll
                for (int i = 0; i < 4; i++)
                    ldsm_x4(aL[i][0], aL[i][1], aL[i][2], aL[i][3],
                            tAlo + (uint32_t)((arow + i * 16) * SPAD + acol) * 2);
                #pragma unroll
                for (int i = 0; i < 4; i++)
                    #pragma unroll
                    for (int j = 0; j < 4; j++)
                        mma_f16(acc[i][j], aL[i], b[j]);
            }
        }
        __syncthreads();
    }

    const int gr = lane >> 2;
    const int gc = (lane & 3) * 2;
    float* C = C_ ? C_ + offC : nullptr;
    __half* Chi = Chi_ ? Chi_ + offC : nullptr;
    __half* Clo = Clo_ ? Clo_ + offC : nullptr;
    __half* Fh = Fh_ ? Fh_ + offC : nullptr;

    #pragma unroll
    for (int j = 0; j < 4; j++) {
        int col = bn + warp_n * 32 + j * 8 + gc;
        if (col >= nValid) continue;
        float2 bv = make_float2(0.f, 0.f);
        if (bias) bv = *(const float2*)(bias + col);
        #pragma unroll
        for (int i = 0; i < 4; i++) {
            int row0 = bm + warp_m * 64 + i * 16 + gr;
            float v00 = acc[i][j][0]*scale + bv.x, v01 = acc[i][j][1]*scale + bv.y;
            float v10 = acc[i][j][2]*scale + bv.x, v11 = acc[i][j][3]*scale + bv.y;
            size_t o0 = (size_t)row0 * ldc + col;
            size_t o1 = (size_t)(row0 + 8) * ldc + col;
            if (Chi) {
                __half h;
                h = __float2half(v00); Chi[o0]   = h; Clo[o0]   = __float2half(v00 - __half2float(h));
                h = __float2half(v01); Chi[o0+1] = h; Clo[o0+1] = __float2half(v01 - __half2float(h));
                h = __float2half(v10); Chi[o1]   = h; Clo[o1]   = __float2half(v10 - __half2float(h));
                h = __float2half(v11); Chi[o1+1] = h; Clo[o1+1] = __float2half(v11 - __half2float(h));
            } else if (Fh) {
                *(__half2*)(Fh + o0) = __floats2half2_rn(v00, v01);
                *(__half2*)(Fh + o1) = __floats2half2_rn(v10, v11);
            } else {
                *(float2*)(C + o0) = make_float2(v00, v01);
                *(float2*)(C + o1) = make_float2(v10, v11);
            }
        }
    }
}

// ---------------- parallel liquid scan (exact affine chunk decomposition) ----------------
__global__ __launch_bounds__(512) void liquid_scan_par(
    const float* __restrict__ I, const float* __restrict__ tau,
    const float* __restrict__ log_dt, float* __restrict__ out) {
    const int b = blockIdx.x;
    const int lg = blockIdx.y;
    const int lane16 = threadIdx.x & 15;
    const int chunk  = threadIdx.x >> 4;
    const int o = lg * 16 + lane16;
    const float dt = expf(log_dt[0]);
    const float r = dt / tau[o];
    const float a = 1.f - r;
    const float* Ib = I + (size_t)b * SS * HH + o;
    const int t0 = chunk * 32;

    float Iv[32];
    #pragma unroll
    for (int i = 0; i < 32; i++) Iv[i] = Ib[(size_t)(t0 + i) * HH];

    float u = 0.f, s = 0.f;
    #pragma unroll
    for (int i = 0; i < 32; i++) {
        float sn = s + r * (u - s);
        u = u + r * (Iv[i] - u);
        s = sn;
    }
    __shared__ float2 dloc[32][16];
    __shared__ float2 st[32][16];
    dloc[chunk][lane16] = make_float2(u, s);
    __syncthreads();

    if (chunk == 0) {
        float a2 = a*a, a4 = a2*a2, a8 = a4*a4, a16 = a8*a8;
        float a32v = a16*a16;
        float a31 = a16*a8*a4*a2*a;
        float c32 = 32.f * r * a31;
        float2 x = make_float2(0.f, 0.f);
        #pragma unroll
        for (int c = 0; c < 32; c++) {
            st[c][lane16] = x;
            float2 d = dloc[c][lane16];
            float nu = a32v * x.x + d.x;
            float ns = c32 * x.x + a32v * x.y + d.y;
            x = make_float2(nu, ns);
        }
    }
    __syncthreads();

    float2 x0 = st[chunk][lane16];
    u = x0.x; s = x0.y;
    float* Ob = out + (size_t)b * SS * HH + o;
    #pragma unroll
    for (int i = 0; i < 32; i++) {
        float sn = s + r * (u - s);
        u = u + r * (Iv[i] - u);
        s = sn;
        Ob[(size_t)(t0 + i) * HH] = tanhf(s);
    }
}

// ---------------- layernorm -> fp16 hi/lo ----------------
__global__ void layernorm_split(const float* __restrict__ in, const float* __restrict__ g,
                                const float* __restrict__ be,
                                __half* __restrict__ hi, __half* __restrict__ lo) {
    int row = blockIdx.x;
    int tid = threadIdx.x;
    const float* p = in + (size_t)row * HH;
    float a = p[tid], b = p[tid + 256];
    float sum = a + b, sq = a*a + b*b;
    __shared__ float s1[8], s2[8];
    #pragma unroll
    for (int o = 16; o; o >>= 1) {
        sum += __shfl_xor_sync(0xffffffffu, sum, o);
        sq  += __shfl_xor_sync(0xffffffffu, sq,  o);
    }
    if ((tid & 31) == 0) { s1[tid>>5] = sum; s2[tid>>5] = sq; }
    __syncthreads();
    sum = 0.f; sq = 0.f;
    #pragma unroll
    for (int i = 0; i < 8; i++) { sum += s1[i]; sq += s2[i]; }
    float mean = sum * (1.f/512.f);
    float var  = sq * (1.f/512.f) - mean*mean;
    float inv = rsqrtf(var + 1e-5f);
    float y0 = (a - mean) * inv * g[tid]       + be[tid];
    float y1 = (b - mean) * inv * g[tid + 256] + be[tid + 256];
    size_t base = (size_t)row * HH;
    __half h0 = __float2half(y0);
    __half h1 = __float2half(y1);
    hi[base + tid]       = h0;
    hi[base + tid + 256] = h1;
    lo[base + tid]       = __float2half(y0 - __half2float(h0));
    lo[base + tid + 256] = __float2half(y1 - __half2float(h1));
}

// ---------------- qkv split: Q/K fp16 [bh][s][d], V fp16 transposed [bh][d pad128][k] ----------------
__global__ void qkv_split_kernel(const float* __restrict__ qkv) {
    int idx = blockIdx.x * blockDim.x + threadIdx.x;
    if (idx >= MM * 1536) return;
    int row = idx / 1536;
    int col = idx - row * 1536;
    int b = row >> 10, s = row & 1023;
    float v = qkv[idx];
    if (col < 512) {
        int hd = col >> 6, d = col & 63;
        g_Qh[((size_t)(b*8 + hd) * 1024 + s) * 64 + d] = __float2half(v);
    } else if (col < 1024) {
        int c = col - 512;
        int hd = c >> 6, d = c & 63;
        g_Kh[((size_t)(b*8 + hd) * 1024 + s) * 64 + d] = __float2half(v);
    } else {
        int c = col - 1024;
        int hd = c >> 6, d = c & 63;
        g_Vth[(size_t)(b*8 + hd) * 131072 + (size_t)d * 1024 + s] = __float2half(v);
    }
}

// ---------------- in-place fp16 softmax over rows of 1024 ----------------
__global__ void softmax_f16_kernel(__half* __restrict__ S) {
    size_t row = blockIdx.x;
    __half* p = S + row * 1024;
    int tid = threadIdx.x;   // 256 threads x 4 halves
    uint2 raw = ((const uint2*)p)[tid];
    __half2 h01 = *(__half2*)&raw.x;
    __half2 h23 = *(__half2*)&raw.y;
    float v0 = __low2float(h01), v1 = __high2float(h01);
    float v2 = __low2float(h23), v3 = __high2float(h23);
    float m = fmaxf(fmaxf(v0, v1), fmaxf(v2, v3));
    __shared__ float red[8];
    #pragma unroll
    for (int o = 16; o; o >>= 1) m = fmaxf(m, __shfl_xor_sync(0xffffffffu, m, o));
    if ((tid & 31) == 0) red[tid>>5] = m;
    __syncthreads();
    m = red[0];
    #pragma unroll
    for (int i = 1; i < 8; i++) m = fmaxf(m, red[i]);
    v0 = __expf(v0 - m); v1 = __expf(v1 - m);
    v2 = __expf(v2 - m); v3 = __expf(v3 - m);
    float sum = v0 + v1 + v2 + v3;
    #pragma unroll
    for (int o = 16; o; o >>= 1) sum += __shfl_xor_sync(0xffffffffu, sum, o);
    __syncthreads();
    if ((tid & 31) == 0) red[tid>>5] = sum;
    __syncthreads();
    sum = 0.f;
    #pragma unroll
    for (int i = 0; i < 8; i++) sum += red[i];
    float inv = 1.f / sum;
    __half2 o01 = __floats2half2_rn(v0 * inv, v1 * inv);
    __half2 o23 = __floats2half2_rn(v2 * inv, v3 * inv);
    uint2 outw;
    outw.x = *(uint32_t*)&o01;
    outw.y = *(uint32_t*)&o23;
    ((uint2*)p)[tid] = outw;
}

// ---------------- host orchestration ----------------
extern "C" void kernel_launch(void* const* d_in, const int* in_sizes, int n_in,
                              void* d_out, int out_size) {
    const int*   x          = (const int*)  d_in[0];
    const float* emb        = (const float*)d_in[1];
    const float* W0         = (const float*)d_in[2];
    const float* b0         = (const float*)d_in[3];
    const float* tau0       = (const float*)d_in[4];
    const float* g0         = (const float*)d_in[5];
    const float* be0        = (const float*)d_in[6];
    const float* W1         = (const float*)d_in[7];
    const float* b1         = (const float*)d_in[8];
    const float* tau1       = (const float*)d_in[9];
    const float* g1         = (const float*)d_in[10];
    const float* be1        = (const float*)d_in[11];
    const float* attn_in_w  = (const float*)d_in[12];
    const float* attn_in_b  = (const float*)d_in[13];
    const float* attn_out_w = (const float*)d_in[14];
    const float* attn_out_b = (const float*)d_in[15];
    const float* out_w      = (const float*)d_in[16];
    const float* out_b      = (const float*)d_in[17];
    const float* log_dt     = (const float*)d_in[18];
    float* out = (float*)d_out;

    float *I, *sbuf, *qkv;
    __half *Ahi, *Alo, *A2hi, *A2lo, *H2;
    __half *W0h, *W1h, *Wqh, *Woh, *Bh, *Qh, *Kh, *Vth, *Sh;
    cudaGetSymbolAddress((void**)&I,      g_I);
    cudaGetSymbolAddress((void**)&sbuf,   g_s);
    cudaGetSymbolAddress((void**)&qkv,    g_qkv);
    cudaGetSymbolAddress((void**)&Ahi,    g_Ahi);
    cudaGetSymbolAddress((void**)&Alo,    g_Alo);
    cudaGetSymbolAddress((void**)&A2hi,   g_A2hi);
    cudaGetSymbolAddress((void**)&A2lo,   g_A2lo);
    cudaGetSymbolAddress((void**)&H2,     g_H2);
    cudaGetSymbolAddress((void**)&Bh,     g_Bh);
    cudaGetSymbolAddress((void**)&W0h,    g_W0h);
    cudaGetSymbolAddress((void**)&W1h,    g_W1h);
    cudaGetSymbolAddress((void**)&Wqh,    g_Wqh);
    cudaGetSymbolAddress((void**)&Woh,    g_Woh);
    cudaGetSymbolAddress((void**)&Qh,     g_Qh);
    cudaGetSymbolAddress((void**)&Kh,     g_Kh);
    cudaGetSymbolAddress((void**)&Vth,    g_Vth);
    cudaGetSymbolAddress((void**)&Sh,     g_Sh);

    cudaFuncSetAttribute(gemm_f16_mma,
                         cudaFuncAttributeMaxDynamicSharedMemorySize, GF_SMEM);

    // merged preprocessing: weight converts + embed+PE split (1 launch)
    prep_kernel<<<(unsigned)((N_PREP + 255)/256), 256>>>(out_w, W0, W1, attn_in_w, attn_out_w, x, emb);

    // 2. liquid layer 0 (fp16: exact A hi/lo x rounded W)
    gemm_f16_mma<<<dim3(4, 32, 1), 256, GF_SMEM>>>(
        Ahi, Alo, W0h, b0, I, nullptr, nullptr, nullptr,
        EE, EE, EE, HH, HH, 1.f, 1, 0,0,0,0,0,0);
    liquid_scan_par<<<dim3(BB, 32), 512>>>(I, tau0, log_dt, sbuf);
    layernorm_split<<<MM, 256>>>(sbuf, g0, be0, Ahi, Alo);

    // 3. liquid layer 1
    gemm_f16_mma<<<dim3(4, 32, 1), 256, GF_SMEM>>>(
        Ahi, Alo, W1h, b1, I, nullptr, nullptr, nullptr,
        HH, HH, HH, HH, HH, 1.f, 1, 0,0,0,0,0,0);
    liquid_scan_par<<<dim3(BB, 32), 512>>>(I, tau1, log_dt, sbuf);
    layernorm_split<<<MM, 256>>>(sbuf, g1, be1, Ahi, Alo);

    // 4. MHA: qkv projection (fp16 2-term A)
    gemm_f16_mma<<<dim3(12, 32, 1), 256, GF_SMEM>>>(
        Ahi, Alo, Wqh, attn_in_b, qkv, nullptr, nullptr, nullptr,
        HH, HH, HH, 3*HH, 3*HH, 1.f, 1, 0,0,0,0,0,0);
    qkv_split_kernel<<<(MM*1536 + 255)/256, 256>>>(qkv);

    // scores = Q @ K^T / 8 (fp16 single-product, batched) -> fp16 scores
    gemm_f16_mma<<<dim3(8, 8, 32), 256, GF_SMEM>>>(
        Qh, nullptr, Kh, nullptr, nullptr, nullptr, nullptr, Sh,
        64, 64, 64, 1024, 1024, 0.125f,
        32, 65536LL, 0, 65536LL, 0, 1LL<<20, 0);

    // in-place fp16 softmax -> P
    softmax_f16_kernel<<<32*1024, 256>>>(Sh);

    // AV = P @ Vt^T (fp16 single product) -> fused fp16 hi/lo split into A2
    gemm_f16_mma<<<dim3(1, 8, 32), 256, GF_SMEM>>>(
        Sh, nullptr, Vth, nullptr, nullptr, A2hi, A2lo, nullptr,
        1024, 1024, 1024, 512, 64, 1.f,
        8, 1LL<<20, 8LL<<20, 131072LL, 8LL*131072, 64LL, 524288LL);

    // out-projection (fp16 2-term A) -> single fp16 H2
    gemm_f16_mma<<<dim3(4, 32, 1), 256, GF_SMEM>>>(
        A2hi, A2lo, Woh, attn_out_b, nullptr, nullptr, nullptr, H2,
        HH, HH, HH, HH, HH, 1.f, 1, 0,0,0,0,0,0);

    // 5. vocab projection (fp16 1-term)
    gemm_f16_mma<<<dim3(VV/128, MM/128, 1), 256, GF_SMEM>>>(
        H2, nullptr, Bh, out_b, out, nullptr, nullptr, nullptr,
        HH, HH, HH, VV, VV, 1.f, 1, 0,0,0,0,0,0);
}